// round 17
// baseline (speedup 1.0000x reference)
#include <cuda_runtime.h>
#include <cuda_bf16.h>
#include <cuda_fp16.h>
#include <cstdint>
#include <math.h>

// ---------------------------------------------------------------------------
// Problem constants
// ---------------------------------------------------------------------------
#define B_   2
#define L_   2521
#define C_   2048
#define H_   16
#define HD_  128
#define M_   (B_ * L_)          // 5042
#define K_   2048
#define KP_  1024               // K/2 u32 pairs per row
#define NQKV 6144
#define VL2  1280               // padded key-pairs per (bh, d) row of g_vt

#define NPX (M_ * KP_)
#define NPW (NQKV * KP_)
#define NPP (C_ * KP_)

__device__ __constant__ int d_cum[10] = {1, 5, 21, 57, 121, 265, 521, 921, 1497, 2521};

// f32 scratch (plain d-order)
__device__ float g_q[B_ * H_ * L_ * HD_];
__device__ float g_k[B_ * H_ * L_ * HD_];
__device__ float g_v[B_ * H_ * L_ * HD_];

// fp16 operands (u32 = packed half2)
__device__ uint32_t g_xf[NPX];               // x         (qkv A, perm4)
__device__ uint32_t g_wf[NPW];               // W_qkv     (qkv B, perm4)
__device__ uint32_t g_qh[B_ * H_ * L_ * 64]; // q         (flash A, perm2)
__device__ uint32_t g_kh[B_ * H_ * L_ * 64]; // k         (flash S-B, perm2)
__device__ uint32_t g_vt[(size_t)B_ * H_ * HD_ * VL2]; // V^T (flash PV-B, perm2)
__device__ uint32_t g_aof[M_ * KP_];         // attn out  (proj A, perm4)
__device__ uint32_t g_pwf[NPP];              // proj_W    (proj B, perm4)

// ---------------------------------------------------------------------------
// helpers
// ---------------------------------------------------------------------------
__device__ __forceinline__ uint32_t pack_h2(float lo, float hi) {
    uint32_t r;
    asm("cvt.rn.f16x2.f32 %0, %1, %2;" : "=r"(r) : "f"(hi), "f"(lo));
    return r;
}

__device__ __forceinline__ void mma16f(float* c,
                                       uint32_t a0, uint32_t a1, uint32_t a2, uint32_t a3,
                                       uint32_t b0, uint32_t b1)
{
    asm volatile(
        "mma.sync.aligned.m16n8k16.row.col.f32.f16.f16.f32 "
        "{%0,%1,%2,%3}, {%4,%5,%6,%7}, {%8,%9}, {%0,%1,%2,%3};"
        : "+f"(c[0]), "+f"(c[1]), "+f"(c[2]), "+f"(c[3])
        : "r"(a0), "r"(a1), "r"(a2), "r"(a3), "r"(b0), "r"(b1));
}

__device__ __forceinline__ uint32_t smaddr(const void* p) {
    return (uint32_t)__cvta_generic_to_shared(p);
}
__device__ __forceinline__ void cp16(uint32_t dst, const void* src, bool pred) {
    int sz = pred ? 16 : 0;
    asm volatile("cp.async.cg.shared.global [%0], [%1], 16, %2;"
                 :: "r"(dst), "l"(src), "r"(sz));
}
__device__ __forceinline__ void cp_commit() {
    asm volatile("cp.async.commit_group;");
}
template<int N>
__device__ __forceinline__ void cp_wait() {
    asm volatile("cp.async.wait_group %0;" :: "n"(N));
}

// perm2: flash layout — pair (t, t+4) of chunk c -> words c*8 + {2t, 2t+1}
__device__ __forceinline__ int pair_perm(int p) {
    int q = p & 15;
    return (p & ~15) + (q & 8) + (q & 3) * 2 + ((q >> 2) & 1);
}
// perm4: GEMM layout — word = t*4 + chunk*2 + hi  (uint4 = frags of BOTH chunks)
__device__ __forceinline__ int perm4(int p) {
    int q = p & 15;
    return (p & ~15) + (q & 3) * 4 + ((q >> 3) & 1) * 2 + ((q >> 2) & 1);
}

// ---------------------------------------------------------------------------
// Kernel 0: fused f32 -> fp16 pack for x, W_qkv, proj_W (perm4 layout)
// ---------------------------------------------------------------------------
__global__ void __launch_bounds__(256)
convert_all(const float* __restrict__ x, const float* __restrict__ W,
            const float* __restrict__ pW)
{
    int i = blockIdx.x * 256 + threadIdx.x;
    const float* src;
    uint32_t* dst;
    if (i < NPX) {
        src = x; dst = g_xf;
    } else if (i < NPX + NPW) {
        i -= NPX; src = W; dst = g_wf;
    } else {
        i -= NPX + NPW;
        if (i >= NPP) return;
        src = pW; dst = g_pwf;
    }
    int row = i >> 10;
    int p = i & 1023;
    float2 v = *(const float2*)(src + (size_t)row * K_ + p * 2);
    dst[(size_t)row * KP_ + perm4(p)] = pack_h2(v.x, v.y);
}

// ---------------------------------------------------------------------------
// Kernel 0c: tiled V transpose -> g_vt (perm2), coalesced stores
// ---------------------------------------------------------------------------
__global__ void __launch_bounds__(256)
vt_transpose()
{
    __shared__ float tile[64][132];
    const int kb = blockIdx.x;
    const int bh = blockIdx.y;
    const int tid = threadIdx.x;
    const int wid = tid >> 5, lane = tid & 31;

    {
        int r = tid >> 2;
        int cb = (tid & 3) * 32;
        int key = kb * 64 + r;
        bool ok = key < L_;
        const float* src = g_v + ((size_t)bh * L_ + (ok ? key : 0)) * HD_ + cb;
#pragma unroll
        for (int i = 0; i < 8; i++) {
            float4 v = ok ? *(const float4*)(src + 4 * i)
                          : make_float4(0.f, 0.f, 0.f, 0.f);
            *(float4*)&tile[r][cb + 4 * i] = v;
        }
    }
    __syncthreads();

#pragma unroll
    for (int it = 0; it < 16; it++) {
        int d = wid * 16 + it;
        float f0 = tile[2 * lane][d];
        float f1 = tile[2 * lane + 1][d];
        int gp = kb * 32 + lane;
        g_vt[((size_t)bh * HD_ + d) * VL2 + pair_perm(gp)] = pack_h2(f0, f1);
    }
}

// ---------------------------------------------------------------------------
// Single-term fp16 GEMM mainloop: C[128x128]=A*B^T, BK=64 (32 u32/row),
// 3-stage cp.async (32 KB stages), XOR swizzle per 16-word block.
// ---------------------------------------------------------------------------
#define GW 32
#define QARR (128 * GW)          // 4096 u32
#define QSTG (2 * QARR)          // 8192 u32 = 32 KB

__device__ __forceinline__ void f16_prefetch(
    uint32_t* sbase, const uint32_t* ag, const uint32_t* bg,
    int ku, bool aok, int r, int fq)
{
    int sw = (r & 3) << 2;
    uint32_t dA = smaddr(sbase + r * GW + fq);
    uint32_t dB = dA + QARR * 4;
#pragma unroll
    for (int i = 0; i < 4; i++) {
        int off = 4 * ((4 * i) ^ sw);
        cp16(dA + off, ag + ku + 4 * i, aok);
        cp16(dB + off, bg + ku + 4 * i, true);
    }
}

__device__ __forceinline__ void f16_core(
    const uint32_t* __restrict__ Ag, const uint32_t* __restrict__ Bg,
    int m0, int n0, uint32_t* smu, float acc[2][8][4], int tid)
{
    const int lane = tid & 31, wid = tid >> 5;
    const int g = lane >> 2, t = lane & 3;
    const int mw = (wid >> 1) * 32, nw = (wid & 1) * 64;

    const int r = tid >> 1;
    const int fq = (tid & 1) * 16;
    const bool aok = (m0 + r) < M_;
    const uint32_t* ag = Ag + (size_t)(aok ? m0 + r : 0) * KP_ + fq;
    const uint32_t* bg = Bg + (size_t)(n0 + r) * KP_ + fq;

    f16_prefetch(smu,            ag, bg, 0,  aok, r, fq);
    cp_commit();
    f16_prefetch(smu + QSTG,     ag, bg, 32, aok, r, fq);
    cp_commit();

    const int wb0 = (4 * t) ^ ((g & 3) << 2);
    const int NIT = KP_ / 32;    // 32

    for (int it = 0; it < NIT; it++) {
        if (it + 1 >= NIT) cp_wait<0>(); else cp_wait<1>();
        __syncthreads();
        if (it + 2 < NIT) {
            f16_prefetch(smu + ((it + 2) % 3) * QSTG, ag, bg, (it + 2) * 32, aok, r, fq);
            cp_commit();
        }

        uint32_t* As = smu + (it % 3) * QSTG;
        uint32_t* Bs = As + QARR;

#pragma unroll
        for (int blk = 0; blk < 2; blk++) {
            const int wb4 = blk * 16 + wb0;
            uint4 va0[2], va1[2];
#pragma unroll
            for (int mi = 0; mi < 2; mi++) {
                int r0 = mw + 16 * mi + g;
                va0[mi] = *(const uint4*)&As[r0 * GW + wb4];
                va1[mi] = *(const uint4*)&As[(r0 + 8) * GW + wb4];
            }
#pragma unroll
            for (int j = 0; j < 8; j++) {
                int cn = nw + 8 * j + g;
                uint4 bb = *(const uint4*)&Bs[cn * GW + wb4];
#pragma unroll
                for (int mi = 0; mi < 2; mi++) {
                    mma16f(acc[mi][j], va0[mi].x, va1[mi].x, va0[mi].y, va1[mi].y, bb.x, bb.y);
                    mma16f(acc[mi][j], va0[mi].z, va1[mi].z, va0[mi].w, va1[mi].w, bb.z, bb.w);
                }
            }
        }
    }
}

// ---------------------------------------------------------------------------
// Kernel 1: QKV GEMM + scatter epilogue (plain f32 q/k/v)
// ---------------------------------------------------------------------------
__global__ void __launch_bounds__(256, 2)
qkv_gemm(const float* __restrict__ qb, const float* __restrict__ vb)
{
    extern __shared__ uint32_t smu[];
    float acc[2][8][4];
#pragma unroll
    for (int a = 0; a < 2; a++)
#pragma unroll
        for (int b = 0; b < 8; b++)
#pragma unroll
            for (int c = 0; c < 4; c++) acc[a][b][c] = 0.f;

    const int tid = threadIdx.x;
    const int lane = tid & 31, wid = tid >> 5;
    const int g = lane >> 2, t = lane & 3;
    const int mw = (wid >> 1) * 32, nw = (wid & 1) * 64;
    const int n0 = blockIdx.x * 128;
    const int m0 = blockIdx.y * 128;

    f16_core(g_xf, g_wf, m0, n0, smu, acc, tid);

    const int tq = n0 >> 11;
    const int h = (n0 & 2047) >> 7;
    float* dst = (tq == 0) ? g_q : ((tq == 1) ? g_k : g_v);

    float2 bias[8];
#pragma unroll
    for (int j = 0; j < 8; j++) {
        int d = nw + 8 * j + 2 * t;
        float b0 = 0.f, b1 = 0.f;
        if (tq == 0) { b0 = qb[h * HD_ + d]; b1 = qb[h * HD_ + d + 1]; }
        else if (tq == 2) { b0 = vb[h * HD_ + d]; b1 = vb[h * HD_ + d + 1]; }
        bias[j] = make_float2(b0, b1);
    }

#pragma unroll
    for (int mi = 0; mi < 2; mi++)
#pragma unroll
        for (int rr = 0; rr < 2; rr++) {
            int gm = m0 + mw + 16 * mi + g + 8 * rr;
            if (gm >= M_) continue;
            int b = gm / L_;
            int l = gm - b * L_;
            float* p = dst + ((size_t)(b * H_ + h) * L_ + l) * HD_;
#pragma unroll
            for (int j = 0; j < 8; j++) {
                float2 o;
                o.x = acc[mi][j][2 * rr] + bias[j].x;
                o.y = acc[mi][j][2 * rr + 1] + bias[j].y;
                *(float2*)(p + nw + 8 * j + 2 * t) = o;
            }
        }
}

// ---------------------------------------------------------------------------
// Kernel 4: proj GEMM (single-term fp16) + bias epilogue
// ---------------------------------------------------------------------------
__global__ void __launch_bounds__(256, 2)
proj_gemm(const float* __restrict__ pb, float* __restrict__ out)
{
    extern __shared__ uint32_t smu[];
    float acc[2][8][4];
#pragma unroll
    for (int a = 0; a < 2; a++)
#pragma unroll
        for (int b = 0; b < 8; b++)
#pragma unroll
            for (int c = 0; c < 4; c++) acc[a][b][c] = 0.f;

    const int tid = threadIdx.x;
    const int lane = tid & 31, wid = tid >> 5;
    const int g = lane >> 2, t = lane & 3;
    const int mw = (wid >> 1) * 32, nw = (wid & 1) * 64;
    const int n0 = blockIdx.x * 128;
    const int m0 = blockIdx.y * 128;

    f16_core(g_aof, g_pwf, m0, n0, smu, acc, tid);

    float2 bias[8];
#pragma unroll
    for (int j = 0; j < 8; j++) {
        int n = n0 + nw + 8 * j + 2 * t;
        bias[j] = make_float2(pb[n], pb[n + 1]);
    }

#pragma unroll
    for (int mi = 0; mi < 2; mi++)
#pragma unroll
        for (int rr = 0; rr < 2; rr++) {
            int gm = m0 + mw + 16 * mi + g + 8 * rr;
            if (gm >= M_) continue;
            float* p = out + (size_t)gm * C_ + n0 + nw;
#pragma unroll
            for (int j = 0; j < 8; j++) {
                float2 o;
                o.x = acc[mi][j][2 * rr] + bias[j].x;
                o.y = acc[mi][j][2 * rr + 1] + bias[j].y;
                *(float2*)(p + 8 * j + 2 * t) = o;
            }
        }
}

// ---------------------------------------------------------------------------
// Kernel 2: norm + rope; writes fp16 perm2 q/k (flash operands)
// ---------------------------------------------------------------------------
__global__ void __launch_bounds__(256)
norm_rope(const float* __restrict__ sml, const float* __restrict__ rope)
{
    const int gw = blockIdx.x * 8 + (threadIdx.x >> 5);
    const int lane = threadIdx.x & 31;
    if (gw >= B_ * H_ * L_) return;
    const int l = gw % L_;
    const int h = (gw / L_) % H_;

    float2 cc = *(const float2*)(rope + (size_t)l * 64 + lane * 2);
    float2 ss = *(const float2*)(rope + (size_t)L_ * 64 + (size_t)l * 64 + lane * 2);
    const float scale = __expf(fminf(sml[h], 4.605170185988091f));
    const size_t base = (size_t)gw * HD_ + lane * 4;
    const int s0 = pair_perm(2 * lane);
    const int s1 = pair_perm(2 * lane + 1);

    {
        float4 v = *(const float4*)(g_q + base);
        float ssq = v.x * v.x + v.y * v.y + v.z * v.z + v.w * v.w;
#pragma unroll
        for (int o = 16; o; o >>= 1) ssq += __shfl_xor_sync(0xffffffffu, ssq, o);
        float inv = scale / fmaxf(sqrtf(ssq), 1e-12f);
        v.x *= inv; v.y *= inv; v.z *= inv; v.w *= inv;
        float rx = cc.x * v.x - ss.x * v.y;
        float ry = ss.x * v.x + cc.x * v.y;
        float rz = cc.y * v.z - ss.y * v.w;
        float rw = ss.y * v.z + cc.y * v.w;
        g_qh[(size_t)gw * 64 + s0] = pack_h2(rx, ry);
        g_qh[(size_t)gw * 64 + s1] = pack_h2(rz, rw);
    }
    {
        float4 v = *(const float4*)(g_k + base);
        float ssq = v.x * v.x + v.y * v.y + v.z * v.z + v.w * v.w;
#pragma unroll
        for (int o = 16; o; o >>= 1) ssq += __shfl_xor_sync(0xffffffffu, ssq, o);
        float inv = 1.f / fmaxf(sqrtf(ssq), 1e-12f);
        v.x *= inv; v.y *= inv; v.z *= inv; v.w *= inv;
        float rx = cc.x * v.x - ss.x * v.y;
        float ry = ss.x * v.x + cc.x * v.y;
        float rz = cc.y * v.z - ss.y * v.w;
        float rw = ss.y * v.z + cc.y * v.w;
        g_kh[(size_t)gw * 64 + s0] = pack_h2(rx, ry);
        g_kh[(size_t)gw * 64 + s1] = pack_h2(rz, rw);
    }
}

// ---------------------------------------------------------------------------
// Kernel 3: flash attention, all-fp16 mma (unchanged from R16)
// ---------------------------------------------------------------------------
#define FKW 64
#define FVW 32
#define KTILE (64 * FKW)
#define VTILE (128 * FVW)
#define FSTG (KTILE + VTILE)

__device__ __forceinline__ int kend_of(int lq) {
    if (lq >= L_) return 0;
    int ke = 2521;
#pragma unroll
    for (int i = 9; i >= 0; i--)
        if (lq < d_cum[i]) ke = d_cum[i];
    return ke;
}

__device__ __forceinline__ void flash_prefetch(
    uint32_t* sm, int s, int it, const uint32_t* kp, const uint32_t* vtp, int tid)
{
    uint32_t* Kb = sm + s * FSTG;
    uint32_t* Vb = Kb + KTILE;
    const int k0 = it * 64;
    {
        int kr = tid >> 2;
        int cb = (tid & 3) * 16;
        bool ok = (k0 + kr) < L_;
        const uint32_t* src = kp + (size_t)(ok ? (k0 + kr) : 0) * 64 + cb;
        int sw = (kr & 7) << 3;
        uint32_t d = smaddr(Kb + kr * FKW);
#pragma unroll
        for (int i = 0; i < 4; i++)
            cp16(d + 4 * ((cb + 4 * i) ^ sw), src + 4 * i, ok);
    }
    {
        int dr = tid >> 1;
        int cb = (tid & 1) * 16;
        const uint32_t* src = vtp + (size_t)dr * VL2 + it * 32 + cb;
        int sw = (dr & 7) << 2;
        uint32_t d = smaddr(Vb + dr * FVW);
#pragma unroll
        for (int i = 0; i < 4; i++)
            cp16(d + 4 * ((cb + 4 * i) ^ sw), src + 4 * i, true);
    }
}

__global__ void __launch_bounds__(256, 1)
flash_attn()
{
    extern __shared__ uint32_t smF[];

    const int bh = blockIdx.y;
    const int q0 = (gridDim.x - 1 - blockIdx.x) * 128;
    const uint32_t* qp = g_qh + (size_t)bh * L_ * 64;
    const uint32_t* kp = g_kh + (size_t)bh * L_ * 64;
    const uint32_t* vtp = g_vt + (size_t)bh * HD_ * VL2;
    const int tid = threadIdx.x, lane = tid & 31, wid = tid >> 5;
    const int g = lane >> 2, t = lane & 3;
    const int rowbase = wid * 16 + g;

    int kmax;
    {
        int lql = min(q0 + 127, L_ - 1);
        kmax = 2521;
#pragma unroll
        for (int i = 9; i >= 0; i--)
            if (lql < d_cum[i]) kmax = d_cum[i];
    }
    const int niter = (kmax + 63) / 64;

    {
        int r = tid >> 1;
        int cb = (tid & 1) * 32;
        bool ok = (q0 + r) < L_;
        const uint32_t* src = qp + (size_t)(ok ? (q0 + r) : 0) * 64 + cb;
        int sw = (r & 7) << 3;
        uint32_t d = smaddr(smF + r * FKW);
#pragma unroll
        for (int i = 0; i < 8; i++)
            cp16(d + 4 * ((cb + 4 * i) ^ sw), src + 4 * i, ok);
    }
    cp_commit();
    flash_prefetch(smF, 1, 0, kp, vtp, tid);
    cp_commit();
    if (niter > 1) flash_prefetch(smF, 2, 1, kp, vtp, tid);
    cp_commit();

    cp_wait<2>();
    __syncthreads();

    uint32_t qf[8][4];
    {
        const int swq = g << 3;
#pragma unroll
        for (int c = 0; c < 8; c++) {
            int wb = (c * 8 + 2 * t) ^ swq;
            uint2 a0 = *(const uint2*)&smF[rowbase * FKW + wb];
            uint2 a1 = *(const uint2*)&smF[(rowbase + 8) * FKW + wb];
            qf[c][0] = a0.x; qf[c][2] = a0.y;
            qf[c][1] = a1.x; qf[c][3] = a1.y;
        }
    }
    __syncthreads();

    const int kend0 = kend_of(q0 + rowbase);
    const int kend1 = kend_of(q0 + rowbase + 8);

    float m0v = -1e30f, m1v = -1e30f, l0v = 0.f, l1v = 0.f;
    float O[16][4];
#pragma unroll
    for (int j = 0; j < 16; j++)
#pragma unroll
        for (int c = 0; c < 4; c++) O[j][c] = 0.f;

    for (int it = 0; it < niter; it++) {
        const int k0 = it * 64;
        if (it + 1 >= niter) cp_wait<0>(); else cp_wait<1>();
        __syncthreads();
        if (it + 2 < niter) {
            flash_prefetch(smF, it % 3, it + 2, kp, vtp, tid);
            cp_commit();
        }

        uint32_t* Kb = smF + ((it + 1) % 3) * FSTG;
        uint32_t* Vt = Kb + KTILE;

        float sc[8][4];
#pragma unroll
        for (int j = 0; j < 8; j++)
#pragma unroll
            for (int c = 0; c < 4; c++) sc[j][c] = 0.f;

        const int swk = g << 3;
#pragma unroll
        for (int c = 0; c < 8; c++) {
            int wb = (c * 8 + 2 * t) ^ swk;
#pragma unroll
            for (int j = 0; j < 8; j++) {
                uint2 bb = *(const uint2*)&Kb[(8 * j + g) * FKW + wb];
                mma16f(sc[j], qf[c][0], qf[c][1], qf[c][2], qf[c][3], bb.x, bb.y);
            }
        }

        float rmax0 = -1e30f, rmax1 = -1e30f;
#pragma unroll
        for (int j = 0; j < 8; j++) {
            int c0 = k0 + 8 * j + 2 * t, c1 = c0 + 1;
            if (c0 >= kend0) sc[j][0] = -1e30f;
            if (c1 >= kend0) sc[j][1] = -1e30f;
            if (c0 >= kend1) sc[j][2] = -1e30f;
            if (c1 >= kend1) sc[j][3] = -1e30f;
            rmax0 = fmaxf(rmax0, fmaxf(sc[j][0], sc[j][1]));
            rmax1 = fmaxf(rmax1, fmaxf(sc[j][2], sc[j][3]));
        }
        rmax0 = fmaxf(rmax0, __shfl_xor_sync(0xffffffffu, rmax0, 1));
        rmax0 = fmaxf(rmax0, __shfl_xor_sync(0xffffffffu, rmax0, 2));
        rmax1 = fmaxf(rmax1, __shfl_xor_sync(0xffffffffu, rmax1, 1));
        rmax1 = fmaxf(rmax1, __shfl_xor_sync(0xffffffffu, rmax1, 2));

        float mn0 = fmaxf(m0v, rmax0), mn1 = fmaxf(m1v, rmax1);
        float al0 = __expf(m0v - mn0), al1 = __expf(m1v - mn1);
        float rs0 = 0.f, rs1 = 0.f;
#pragma unroll
        for (int j = 0; j < 8; j++) {
            float p0 = (sc[j][0] > -5e29f) ? __expf(sc[j][0] - mn0) : 0.f;
            float p1 = (sc[j][1] > -5e29f) ? __expf(sc[j][1] - mn0) : 0.f;
            float p2 = (sc[j][2] > -5e29f) ? __expf(sc[j][2] - mn1) : 0.f;
            float p3 = (sc[j][3] > -5e29f) ? __expf(sc[j][3] - mn1) : 0.f;
            rs0 += p0 + p1;
            rs1 += p2 + p3;
            sc[j][0] = p0; sc[j][1] = p1; sc[j][2] = p2; sc[j][3] = p3;
        }
        rs0 += __shfl_xor_sync(0xffffffffu, rs0, 1);
        rs0 += __shfl_xor_sync(0xffffffffu, rs0, 2);
        rs1 += __shfl_xor_sync(0xffffffffu, rs1, 1);
        rs1 += __shfl_xor_sync(0xffffffffu, rs1, 2);
        l0v = l0v * al0 + rs0;
        l1v = l1v * al1 + rs1;
        m0v = mn0; m1v = mn1;

#pragma unroll
        for (int j = 0; j < 16; j++) {
            O[j][0] *= al0; O[j][1] *= al0;
            O[j][2] *= al1; O[j][3] *= al1;
        }

        const int swv = g << 2;
#pragma unroll
        for (int c = 0; c < 4; c++) {
            uint32_t a0 = pack_h2(sc[2 * c][0],     sc[2 * c][1]);
            uint32_t a1 = pack_h2(sc[2 * c][2],     sc[2 * c][3]);
            uint32_t a2 = pack_h2(sc[2 * c + 1][0], sc[2 * c + 1][1]);
            uint32_t a3 = pack_h2(sc[2 * c + 1][2], sc[2 * c + 1][3]);
            int wv = (c * 8 + 2 * t) ^ swv;
#pragma unroll
            for (int j = 0; j < 16; j++) {
                uint2 bb = *(const uint2*)&Vt[(8 * j + g) * FVW + wv];
                mma16f(O[j], a0, a1, a2, a3, bb.x, bb.y);
            }
        }
    }

    // epilogue: normalize, single fp16 pair store (perm4 layout for proj)
    const int b = bh >> 4;
    const int h = bh & 15;
#pragma unroll
    for (int rr = 0; rr < 2; rr++) {
        int lq = q0 + rowbase + 8 * rr;
        if (lq >= L_) continue;
        float inv = 1.f / (rr ? l1v : l0v);
        size_t rowoff = (size_t)(b * L_ + lq) * KP_;
#pragma unroll
        for (int j = 0; j < 16; j++) {
            float x0 = O[j][2 * rr] * inv;
            float x1 = O[j][2 * rr + 1] * inv;
            int p = h * 64 + 4 * j + t;
            g_aof[rowoff + perm4(p)] = pack_h2(x0, x1);
        }
    }
}

// ---------------------------------------------------------------------------
// launch
// ---------------------------------------------------------------------------
extern "C" void kernel_launch(void* const* d_in, const int* in_sizes, int n_in,
                              void* d_out, int out_size)
{
    const float* x    = (const float*)d_in[0];
    const float* Wqkv = (const float*)d_in[1];
    const float* qb   = (const float*)d_in[2];
    const float* vb   = (const float*)d_in[3];
    const float* sml  = (const float*)d_in[4];
    const float* pW   = (const float*)d_in[5];
    const float* pb   = (const float*)d_in[6];
    const float* rope = (const float*)d_in[7];
    float* out = (float*)d_out;

    const size_t gemm_shm  = (size_t)3 * QSTG * sizeof(uint32_t);     // 98,304 B
    const size_t flash_shm = (size_t)3 * FSTG * sizeof(uint32_t);     // 98,304 B

    cudaFuncSetAttribute(qkv_gemm, cudaFuncAttributeMaxDynamicSharedMemorySize, (int)gemm_shm);
    cudaFuncSetAttribute(proj_gemm, cudaFuncAttributeMaxDynamicSharedMemorySize, (int)gemm_shm);
    cudaFuncSetAttribute(flash_attn, cudaFuncAttributeMaxDynamicSharedMemorySize, (int)flash_shm);

    {
        int np = NPX + NPW + NPP;
        convert_all<<<(np + 255) / 256, 256>>>(x, Wqkv, pW);
    }

    dim3 g1(NQKV / 128, (M_ + 127) / 128);   // 48 x 40
    qkv_gemm<<<g1, 256, gemm_shm>>>(qb, vb);

    int nwarps = B_ * H_ * L_;
    norm_rope<<<(nwarps + 7) / 8, 256>>>(sml, rope);

    {
        dim3 gv(40, B_ * H_);
        vt_transpose<<<gv, 256>>>();
    }

    dim3 g3((L_ + 127) / 128, B_ * H_);      // 20 x 32
    flash_attn<<<g3, 256, flash_shm>>>();

    dim3 g4(C_ / 128, (M_ + 127) / 128);     // 16 x 40
    proj_gemm<<<g4, 256, gemm_shm>>>(pb, out);
}